// round 3
// baseline (speedup 1.0000x reference)
#include <cuda_runtime.h>
#include <cstdint>

#define N_NODES 40000
#define N_EDGES 640000
#define IN_DIM  128
#define HID     256

// ---------------- device scratch (static, no allocations) ----------------
__device__ int   g_is64;                    // 1 if edge_index is int64, 0 if int32
__device__ int   g_srcs[N_EDGES];           // normalized int32 src per edge
__device__ int   g_dsts[N_EDGES];           // normalized int32 dst per edge
__device__ int   g_count[N_NODES];
__device__ int   g_rowstart[N_NODES + 1];
__device__ int   g_cursor[N_NODES];
__device__ int   g_src[N_EDGES];            // CSR adjacency (src ids, grouped by dst)
__device__ __align__(16) float g_agg[(size_t)N_NODES * HID];
__device__ __align__(16) float g_h  [(size_t)N_NODES * HID];
__device__ __align__(16) float g_h2 [(size_t)N_NODES * HID];

// ---------------- edge-index dtype detection + normalization ----------------
// If the buffer is int64 (non-negative values < 40000), every odd 32-bit word
// (little-endian high half) is zero. If int32, odd words are edge ids
// (2048 random values in [0,40000) all being zero has ~0 probability).
__global__ void k_detect(const int* __restrict__ ei_w) {
    __shared__ int acc;
    if (threadIdx.x == 0) acc = 0;
    __syncthreads();
    int v = 0;
    for (int i = threadIdx.x; i < 2048; i += 256) v |= ei_w[2 * i + 1];
    atomicOr(&acc, v);
    __syncthreads();
    if (threadIdx.x == 0) g_is64 = (acc == 0) ? 1 : 0;
}

__device__ __forceinline__ int clampN(int v) {
    return v < 0 ? 0 : (v >= N_NODES ? N_NODES - 1 : v);
}

__global__ void k_extract(const int* __restrict__ ei_w) {
    int e = blockIdx.x * blockDim.x + threadIdx.x;
    if (e >= N_EDGES) return;
    int s, d;
    if (g_is64) {
        s = ei_w[2 * (size_t)e];
        d = ei_w[2 * ((size_t)N_EDGES + e)];
    } else {
        s = ei_w[e];
        d = ei_w[N_EDGES + e];
    }
    g_srcs[e] = clampN(s);
    g_dsts[e] = clampN(d);
}

// ---------------- CSR build ----------------
__global__ void k_zero_counts() {
    int i = blockIdx.x * blockDim.x + threadIdx.x;
    if (i < N_NODES) g_count[i] = 0;
}

__global__ void k_count_dst() {
    int e = blockIdx.x * blockDim.x + threadIdx.x;
    if (e < N_EDGES) atomicAdd(&g_count[g_dsts[e]], 1);
}

// one block of 1024 threads: exclusive scan over 40000 counts
__global__ void k_scan_counts() {
    __shared__ int part[1024];
    const int t   = threadIdx.x;
    const int PER = (N_NODES + 1023) / 1024;   // 40
    const int base = t * PER;
    int s = 0;
    for (int j = 0; j < PER; j++) {
        int idx = base + j;
        if (idx < N_NODES) s += g_count[idx];
    }
    part[t] = s;
    __syncthreads();
    for (int off = 1; off < 1024; off <<= 1) {
        int v = (t >= off) ? part[t - off] : 0;
        __syncthreads();
        part[t] += v;
        __syncthreads();
    }
    int run = (t == 0) ? 0 : part[t - 1];
    for (int j = 0; j < PER; j++) {
        int idx = base + j;
        if (idx < N_NODES) {
            g_rowstart[idx] = run;
            g_cursor[idx]   = run;
            run += g_count[idx];
        }
    }
    if (t == 1023) g_rowstart[N_NODES] = part[1023];
}

__global__ void k_fill_src() {
    int e = blockIdx.x * blockDim.x + threadIdx.x;
    if (e < N_EDGES) {
        int pos = atomicAdd(&g_cursor[g_dsts[e]], 1);
        g_src[pos] = g_srcs[e];
    }
}

// ---------------- mean aggregation over in-edges ----------------
// D/4 threads per node, float4 lanes; 256 threads/block.
template <int D>
__global__ void k_aggregate(const float* __restrict__ x, float* __restrict__ out) {
    constexpr int TPN = D / 4;        // threads per node
    constexpr int NPB = 256 / TPN;    // nodes per block
    int node = blockIdx.x * NPB + threadIdx.x / TPN;
    int lane = threadIdx.x % TPN;
    if (node >= N_NODES) return;

    const int beg = g_rowstart[node];
    const int end = g_rowstart[node + 1];
    const float4* xv = (const float4*)x;

    float ax = 0.f, ay = 0.f, az = 0.f, aw = 0.f;
    int j = beg;
    for (; j + 4 <= end; j += 4) {
        int s0 = g_src[j + 0], s1 = g_src[j + 1], s2 = g_src[j + 2], s3 = g_src[j + 3];
        float4 v0 = xv[(size_t)s0 * TPN + lane];
        float4 v1 = xv[(size_t)s1 * TPN + lane];
        float4 v2 = xv[(size_t)s2 * TPN + lane];
        float4 v3 = xv[(size_t)s3 * TPN + lane];
        ax += v0.x + v1.x + v2.x + v3.x;
        ay += v0.y + v1.y + v2.y + v3.y;
        az += v0.z + v1.z + v2.z + v3.z;
        aw += v0.w + v1.w + v2.w + v3.w;
    }
    for (; j < end; j++) {
        float4 v = xv[(size_t)g_src[j] * TPN + lane];
        ax += v.x; ay += v.y; az += v.z; aw += v.w;
    }
    float inv = (end > beg) ? 1.f / (float)(end - beg) : 0.f;
    float4 r = make_float4(ax * inv, ay * inv, az * inv, aw * inv);
    ((float4*)out)[(size_t)node * TPN + lane] = r;
}

// ---------------- fused dual-source GEMM ----------------
// C[M, 256] = A0 @ W0^T + A1 @ W1^T + b   (optionally ReLU)
// BM=BN=64, BK=16, 256 threads, 4x4 microtile. M = 40000 = 625*64 exactly.
__global__ __launch_bounds__(256)
void k_sage_gemm(const float* __restrict__ A0, const float* __restrict__ W0,
                 const float* __restrict__ A1, const float* __restrict__ W1,
                 int K, const float* __restrict__ bias,
                 float* __restrict__ C, int do_relu) {
    constexpr int BM = 64, BN = 64, BK = 16;
    __shared__ float As[BK][BM + 4];
    __shared__ float Ws[BK][BN + 4];

    const int t   = threadIdx.x;
    const int tx  = t & 15;
    const int ty  = t >> 4;
    const int row0 = blockIdx.x * BM;
    const int col0 = blockIdx.y * BN;
    const int lr = t >> 2;             // 0..63 tile row for loading
    const int lk = (t & 3) * 4;        // 0,4,8,12 k-offset for loading

    float acc[4][4] = {};

    #pragma unroll 1
    for (int srcSel = 0; srcSel < 2; ++srcSel) {
        const float* A = srcSel ? A1 : A0;
        const float* W = srcSel ? W1 : W0;
        for (int kt = 0; kt < K; kt += BK) {
            float4 av = *(const float4*)&A[(size_t)(row0 + lr) * K + kt + lk];
            float4 wv = *(const float4*)&W[(size_t)(col0 + lr) * K + kt + lk];
            __syncthreads();
            As[lk + 0][lr] = av.x; As[lk + 1][lr] = av.y;
            As[lk + 2][lr] = av.z; As[lk + 3][lr] = av.w;
            Ws[lk + 0][lr] = wv.x; Ws[lk + 1][lr] = wv.y;
            Ws[lk + 2][lr] = wv.z; Ws[lk + 3][lr] = wv.w;
            __syncthreads();
            #pragma unroll
            for (int kk = 0; kk < BK; kk++) {
                float4 a = *(const float4*)&As[kk][ty * 4];
                float4 w = *(const float4*)&Ws[kk][tx * 4];
                acc[0][0] += a.x * w.x; acc[0][1] += a.x * w.y;
                acc[0][2] += a.x * w.z; acc[0][3] += a.x * w.w;
                acc[1][0] += a.y * w.x; acc[1][1] += a.y * w.y;
                acc[1][2] += a.y * w.z; acc[1][3] += a.y * w.w;
                acc[2][0] += a.z * w.x; acc[2][1] += a.z * w.y;
                acc[2][2] += a.z * w.z; acc[2][3] += a.z * w.w;
                acc[3][0] += a.w * w.x; acc[3][1] += a.w * w.y;
                acc[3][2] += a.w * w.z; acc[3][3] += a.w * w.w;
            }
        }
    }

    const int c = col0 + tx * 4;
    float4 bv = *(const float4*)&bias[c];
    #pragma unroll
    for (int i = 0; i < 4; i++) {
        int r = row0 + ty * 4 + i;
        float4 v;
        v.x = acc[i][0] + bv.x;
        v.y = acc[i][1] + bv.y;
        v.z = acc[i][2] + bv.z;
        v.w = acc[i][3] + bv.w;
        if (do_relu) {
            v.x = fmaxf(v.x, 0.f); v.y = fmaxf(v.y, 0.f);
            v.z = fmaxf(v.z, 0.f); v.w = fmaxf(v.w, 0.f);
        }
        *(float4*)&C[(size_t)r * HID + c] = v;
    }
}

// ---------------- launch ----------------
extern "C" void kernel_launch(void* const* d_in, const int* in_sizes, int n_in,
                              void* d_out, int out_size) {
    const float* x   = (const float*)d_in[0];
    const int*   eiw = (const int*)d_in[1];       // raw words; dtype detected on device
    const float* Wl1 = (const float*)d_in[2];
    const float* Wr1 = (const float*)d_in[3];
    const float* b1  = (const float*)d_in[4];
    const float* Wl2 = (const float*)d_in[5];
    const float* Wr2 = (const float*)d_in[6];
    const float* b2  = (const float*)d_in[7];
    const float* Wl3 = (const float*)d_in[8];
    const float* Wr3 = (const float*)d_in[9];
    const float* b3  = (const float*)d_in[10];
    float*       out = (float*)d_out;

    float *agg, *h, *h2;
    cudaGetSymbolAddress((void**)&agg, g_agg);
    cudaGetSymbolAddress((void**)&h,   g_h);
    cudaGetSymbolAddress((void**)&h2,  g_h2);

    // Edge dtype detection + normalization, then CSR build
    k_detect<<<1, 256>>>(eiw);
    k_extract<<<(N_EDGES + 255) / 256, 256>>>(eiw);
    k_zero_counts<<<(N_NODES + 255) / 256, 256>>>();
    k_count_dst<<<(N_EDGES + 255) / 256, 256>>>();
    k_scan_counts<<<1, 1024>>>();
    k_fill_src<<<(N_EDGES + 255) / 256, 256>>>();

    dim3 ggrid(N_NODES / 64, HID / 64);   // 625 x 4

    // Layer 1: 128 -> 256, relu
    k_aggregate<IN_DIM><<<(N_NODES + 7) / 8, 256>>>(x, agg);
    k_sage_gemm<<<ggrid, 256>>>(agg, Wl1, x, Wr1, IN_DIM, b1, h, 1);

    // Layer 2: 256 -> 256, relu
    k_aggregate<HID><<<(N_NODES + 3) / 4, 256>>>(h, agg);
    k_sage_gemm<<<ggrid, 256>>>(agg, Wl2, h, Wr2, HID, b2, h2, 1);

    // Layer 3: 256 -> 256, no relu, write d_out
    k_aggregate<HID><<<(N_NODES + 3) / 4, 256>>>(h2, agg);
    k_sage_gemm<<<ggrid, 256>>>(agg, Wl3, h2, Wr3, HID, b3, out, 0);
}

// round 4
// speedup vs baseline: 2.0080x; 2.0080x over previous
#include <cuda_runtime.h>
#include <cstdint>

#define N_NODES 40000
#define N_EDGES 640000
#define IN_DIM  128
#define HID     256

// ---------------- device scratch (static, no allocations) ----------------
__device__ int   g_is64;
__device__ int   g_srcs[N_EDGES];
__device__ int   g_dsts[N_EDGES];
__device__ int   g_count[N_NODES];
__device__ int   g_rowstart[N_NODES + 1];
__device__ int   g_cursor[N_NODES];
__device__ int   g_src[N_EDGES];
__device__ __align__(16) float g_agg[(size_t)N_NODES * HID];
__device__ __align__(16) float g_h  [(size_t)N_NODES * HID];
__device__ __align__(16) float g_h2 [(size_t)N_NODES * HID];

// ---------------- edge-index dtype detection + normalization ----------------
__global__ void k_detect(const int* __restrict__ ei_w) {
    __shared__ int acc;
    if (threadIdx.x == 0) acc = 0;
    __syncthreads();
    int v = 0;
    for (int i = threadIdx.x; i < 2048; i += 256) v |= ei_w[2 * i + 1];
    atomicOr(&acc, v);
    __syncthreads();
    if (threadIdx.x == 0) g_is64 = (acc == 0) ? 1 : 0;
}

__device__ __forceinline__ int clampN(int v) {
    return v < 0 ? 0 : (v >= N_NODES ? N_NODES - 1 : v);
}

__global__ void k_extract(const int* __restrict__ ei_w) {
    int e = blockIdx.x * blockDim.x + threadIdx.x;
    if (e >= N_EDGES) return;
    int s, d;
    if (g_is64) {
        s = ei_w[2 * (size_t)e];
        d = ei_w[2 * ((size_t)N_EDGES + e)];
    } else {
        s = ei_w[e];
        d = ei_w[N_EDGES + e];
    }
    g_srcs[e] = clampN(s);
    g_dsts[e] = clampN(d);
}

// ---------------- CSR build ----------------
__global__ void k_zero_counts() {
    int i = blockIdx.x * blockDim.x + threadIdx.x;
    if (i < N_NODES) g_count[i] = 0;
}

__global__ void k_count_dst() {
    int e = blockIdx.x * blockDim.x + threadIdx.x;
    if (e < N_EDGES) atomicAdd(&g_count[g_dsts[e]], 1);
}

__global__ void k_scan_counts() {
    __shared__ int part[1024];
    const int t   = threadIdx.x;
    const int PER = (N_NODES + 1023) / 1024;   // 40
    const int base = t * PER;
    int s = 0;
    for (int j = 0; j < PER; j++) {
        int idx = base + j;
        if (idx < N_NODES) s += g_count[idx];
    }
    part[t] = s;
    __syncthreads();
    for (int off = 1; off < 1024; off <<= 1) {
        int v = (t >= off) ? part[t - off] : 0;
        __syncthreads();
        part[t] += v;
        __syncthreads();
    }
    int run = (t == 0) ? 0 : part[t - 1];
    for (int j = 0; j < PER; j++) {
        int idx = base + j;
        if (idx < N_NODES) {
            g_rowstart[idx] = run;
            g_cursor[idx]   = run;
            run += g_count[idx];
        }
    }
    if (t == 1023) g_rowstart[N_NODES] = part[1023];
}

__global__ void k_fill_src() {
    int e = blockIdx.x * blockDim.x + threadIdx.x;
    if (e < N_EDGES) {
        int pos = atomicAdd(&g_cursor[g_dsts[e]], 1);
        g_src[pos] = g_srcs[e];
    }
}

// ---------------- mean aggregation over in-edges ----------------
template <int D>
__global__ void k_aggregate(const float* __restrict__ x, float* __restrict__ out) {
    constexpr int TPN = D / 4;
    constexpr int NPB = 256 / TPN;
    int node = blockIdx.x * NPB + threadIdx.x / TPN;
    int lane = threadIdx.x % TPN;
    if (node >= N_NODES) return;

    const int beg = g_rowstart[node];
    const int end = g_rowstart[node + 1];
    const float4* xv = (const float4*)x;

    float ax = 0.f, ay = 0.f, az = 0.f, aw = 0.f;
    int j = beg;
    for (; j + 4 <= end; j += 4) {
        int s0 = g_src[j + 0], s1 = g_src[j + 1], s2 = g_src[j + 2], s3 = g_src[j + 3];
        float4 v0 = xv[(size_t)s0 * TPN + lane];
        float4 v1 = xv[(size_t)s1 * TPN + lane];
        float4 v2 = xv[(size_t)s2 * TPN + lane];
        float4 v3 = xv[(size_t)s3 * TPN + lane];
        ax += v0.x + v1.x + v2.x + v3.x;
        ay += v0.y + v1.y + v2.y + v3.y;
        az += v0.z + v1.z + v2.z + v3.z;
        aw += v0.w + v1.w + v2.w + v3.w;
    }
    for (; j < end; j++) {
        float4 v = xv[(size_t)g_src[j] * TPN + lane];
        ax += v.x; ay += v.y; az += v.z; aw += v.w;
    }
    float inv = (end > beg) ? 1.f / (float)(end - beg) : 0.f;
    float4 r = make_float4(ax * inv, ay * inv, az * inv, aw * inv);
    ((float4*)out)[(size_t)node * TPN + lane] = r;
}

// ---------------- tf32 tensor-core fused dual-source GEMM ----------------
// C[M, 256] = A0 @ W0^T + A1 @ W1^T + b   (optional ReLU)
// BM=BN=128, BK=32, 256 threads (8 warps: 4 along M x 2 along N).
// Warp tile 32x64 -> 2 (m16) x 8 (n8) mma.sync.m16n8k8.tf32 tiles.
__device__ __forceinline__ uint32_t f2tf32(float v) {
    uint32_t o;
    asm("cvt.rna.tf32.f32 %0, %1;" : "=r"(o) : "f"(v));
    return o;
}

__device__ __forceinline__ void mma_tf32(float* c,
                                         uint32_t a0, uint32_t a1, uint32_t a2, uint32_t a3,
                                         uint32_t b0, uint32_t b1) {
    asm volatile(
        "mma.sync.aligned.m16n8k8.row.col.f32.tf32.tf32.f32 "
        "{%0,%1,%2,%3}, {%4,%5,%6,%7}, {%8,%9}, {%0,%1,%2,%3};"
        : "+f"(c[0]), "+f"(c[1]), "+f"(c[2]), "+f"(c[3])
        : "r"(a0), "r"(a1), "r"(a2), "r"(a3), "r"(b0), "r"(b1));
}

__global__ __launch_bounds__(256, 2)
void k_sage_gemm_tc(const float* __restrict__ A0, const float* __restrict__ W0,
                    const float* __restrict__ A1, const float* __restrict__ W1,
                    int K, const float* __restrict__ bias,
                    float* __restrict__ C, int do_relu) {
    constexpr int BM = 128, BN = 128, BK = 32;
    constexpr int LDS = BK + 4;                 // 36 floats: frag reads conflict-free (4g+t)
    __shared__ uint32_t As[BM][LDS];
    __shared__ uint32_t Bs[BN][LDS];

    const int t    = threadIdx.x;
    const int warp = t >> 5, lane = t & 31;
    const int g    = lane >> 2, tg = lane & 3;  // groupID, threadID-in-group
    const int wm   = warp & 3;                  // 0..3 -> M offset 32*wm
    const int wn   = warp >> 2;                 // 0..1 -> N offset 64*wn
    const int row0 = blockIdx.x * BM;
    const int col0 = blockIdx.y * BN;

    const int lr = t >> 3;                      // 0..31 load row
    const int kq = t & 7;                       // 0..7  load k-quad

    float acc[2][8][4] = {};

    #pragma unroll 1
    for (int srcSel = 0; srcSel < 2; ++srcSel) {
        const float* A = srcSel ? A1 : A0;
        const float* W = srcSel ? W1 : W0;
        for (int kt = 0; kt < K; kt += BK) {
            __syncthreads();
            #pragma unroll
            for (int i = 0; i < 4; i++) {
                int row = lr + 32 * i;
                float4 av = make_float4(0.f, 0.f, 0.f, 0.f);
                if (row0 + row < N_NODES)
                    av = *(const float4*)&A[(size_t)(row0 + row) * K + kt + kq * 4];
                As[row][kq * 4 + 0] = f2tf32(av.x);
                As[row][kq * 4 + 1] = f2tf32(av.y);
                As[row][kq * 4 + 2] = f2tf32(av.z);
                As[row][kq * 4 + 3] = f2tf32(av.w);
                float4 wv = *(const float4*)&W[(size_t)(col0 + row) * K + kt + kq * 4];
                Bs[row][kq * 4 + 0] = f2tf32(wv.x);
                Bs[row][kq * 4 + 1] = f2tf32(wv.y);
                Bs[row][kq * 4 + 2] = f2tf32(wv.z);
                Bs[row][kq * 4 + 3] = f2tf32(wv.w);
            }
            __syncthreads();

            #pragma unroll
            for (int kk = 0; kk < BK; kk += 8) {
                uint32_t bf[8][2];
                #pragma unroll
                for (int nt = 0; nt < 8; nt++) {
                    int n = wn * 64 + nt * 8 + g;
                    bf[nt][0] = Bs[n][kk + tg];
                    bf[nt][1] = Bs[n][kk + tg + 4];
                }
                #pragma unroll
                for (int mt = 0; mt < 2; mt++) {
                    int r = wm * 32 + mt * 16 + g;
                    uint32_t a0 = As[r    ][kk + tg];
                    uint32_t a1 = As[r + 8][kk + tg];
                    uint32_t a2 = As[r    ][kk + tg + 4];
                    uint32_t a3 = As[r + 8][kk + tg + 4];
                    #pragma unroll
                    for (int nt = 0; nt < 8; nt++)
                        mma_tf32(acc[mt][nt], a0, a1, a2, a3, bf[nt][0], bf[nt][1]);
                }
            }
        }
    }

    // epilogue: bias (+ReLU), predicated rows
    #pragma unroll
    for (int mt = 0; mt < 2; mt++) {
        int r = row0 + wm * 32 + mt * 16 + g;
        #pragma unroll
        for (int nt = 0; nt < 8; nt++) {
            int col = col0 + wn * 64 + nt * 8 + tg * 2;
            float2 bv = *(const float2*)&bias[col];
            float v0 = acc[mt][nt][0] + bv.x;
            float v1 = acc[mt][nt][1] + bv.y;
            float v2 = acc[mt][nt][2] + bv.x;
            float v3 = acc[mt][nt][3] + bv.y;
            if (do_relu) {
                v0 = fmaxf(v0, 0.f); v1 = fmaxf(v1, 0.f);
                v2 = fmaxf(v2, 0.f); v3 = fmaxf(v3, 0.f);
            }
            if (r < N_NODES)     *(float2*)&C[(size_t)r * HID + col]       = make_float2(v0, v1);
            if (r + 8 < N_NODES) *(float2*)&C[(size_t)(r + 8) * HID + col] = make_float2(v2, v3);
        }
    }
}

// ---------------- launch ----------------
extern "C" void kernel_launch(void* const* d_in, const int* in_sizes, int n_in,
                              void* d_out, int out_size) {
    const float* x   = (const float*)d_in[0];
    const int*   eiw = (const int*)d_in[1];
    const float* Wl1 = (const float*)d_in[2];
    const float* Wr1 = (const float*)d_in[3];
    const float* b1  = (const float*)d_in[4];
    const float* Wl2 = (const float*)d_in[5];
    const float* Wr2 = (const float*)d_in[6];
    const float* b2  = (const float*)d_in[7];
    const float* Wl3 = (const float*)d_in[8];
    const float* Wr3 = (const float*)d_in[9];
    const float* b3  = (const float*)d_in[10];
    float*       out = (float*)d_out;

    float *agg, *h, *h2;
    cudaGetSymbolAddress((void**)&agg, g_agg);
    cudaGetSymbolAddress((void**)&h,   g_h);
    cudaGetSymbolAddress((void**)&h2,  g_h2);

    // Edge dtype detection + normalization, then CSR build
    k_detect<<<1, 256>>>(eiw);
    k_extract<<<(N_EDGES + 255) / 256, 256>>>(eiw);
    k_zero_counts<<<(N_NODES + 255) / 256, 256>>>();
    k_count_dst<<<(N_EDGES + 255) / 256, 256>>>();
    k_scan_counts<<<1, 1024>>>();
    k_fill_src<<<(N_EDGES + 255) / 256, 256>>>();

    dim3 ggrid((N_NODES + 127) / 128, HID / 128);   // 313 x 2

    // Layer 1: 128 -> 256, relu
    k_aggregate<IN_DIM><<<(N_NODES + 7) / 8, 256>>>(x, agg);
    k_sage_gemm_tc<<<ggrid, 256>>>(agg, Wl1, x, Wr1, IN_DIM, b1, h, 1);

    // Layer 2: 256 -> 256, relu
    k_aggregate<HID><<<(N_NODES + 3) / 4, 256>>>(h, agg);
    k_sage_gemm_tc<<<ggrid, 256>>>(agg, Wl2, h, Wr2, HID, b2, h2, 1);

    // Layer 3: 256 -> 256, no relu, write d_out
    k_aggregate<HID><<<(N_NODES + 3) / 4, 256>>>(h2, agg);
    k_sage_gemm_tc<<<ggrid, 256>>>(agg, Wl3, h2, Wr3, HID, b3, out, 0);
}